// round 16
// baseline (speedup 1.0000x reference)
#include <cuda_runtime.h>
#include <cuda_fp16.h>
#include <math.h>
#include <stdint.h>

#define NA      10000
#define NE      256000
#define FDIM    128
#define NRBF_K  20
#define NLAYERS 3
#define NMOLS   100
#define NF      (NA*FDIM)               // 1,280,000
#define PHI_D   384
#define CUT_R   5.0f
#define EPS_F   1e-8f
#define PI_F    3.14159265358979323846f

// ---------------- scratch (device globals; no allocations allowed) ----------
__device__ float  g_rbfs[NE*NRBF_K];    // rbf * fcut, CSR-sorted
__device__ float  g_unit[NE*3];         // CSR-sorted
__device__ float  g_fc  [NE];           // fcut, CSR-sorted
__device__ int    g_sj  [NE];           // j per CSR slot
__device__ int    g_cnt [NA];
__device__ int    g_roff[NA+1];
__device__ int    g_cur [NA];
__device__ float  g_s1  [NF];
__device__ float  g_s2  [NF];
__device__ float  g_v1  [3*NF];
__device__ float  g_v2  [3*NF];
__device__ __half g_phih[NA*PHI_D];     // phi in fp16 (gather copy)
__device__ __half g_v1h [3*NF];         // v1 in fp16 (gather copy)
__device__ float  g_hid [NF];
__device__ float  g_uvvv[(size_t)3*NA*256];
__device__ float  g_aw  [NA*PHI_D];
__device__ float  g_Bcat[NLAYERS*FDIM*256];  // [l][k][ U | V ]

__device__ __forceinline__ float totf(float x) {
    float r; asm("cvt.rna.tf32.f32 %0, %1;" : "=f"(r) : "f"(x)); return r;
}

// ---------------- fused prep: s/v init, cnt zero, Bcat -----------------------
__global__ void k_prep0(const float* __restrict__ emb, const int* __restrict__ z,
                        const float* __restrict__ U, const float* __restrict__ V) {
    int idx = blockIdx.x*blockDim.x + threadIdx.x;
    if (idx < NF) {
        int n = idx >> 7, ff = idx & 127;
        g_s1[idx] = emb[z[n]*FDIM + ff];
        g_v1[idx] = 0.f; g_v1[idx + NF] = 0.f; g_v1[idx + 2*NF] = 0.f;
        const __half hz = __float2half(0.f);
        g_v1h[idx] = hz; g_v1h[idx + NF] = hz; g_v1h[idx + 2*NF] = hz;
    }
    if (idx < NA) g_cnt[idx] = 0;
    if (idx < NLAYERS*FDIM*256) {
        int l = idx >> 15, rem = idx & 32767, k = rem >> 8, gg = rem & 255;
        g_Bcat[idx] = (gg < 128) ? U[l*16384 + k*128 + gg] : V[l*16384 + k*128 + gg - 128];
    }
}

// ---------------- CSR build --------------------------------------------------
__global__ void k_count(const int* __restrict__ nbrs) {
    int e = blockIdx.x*blockDim.x + threadIdx.x;
    if (e < NE) atomicAdd(&g_cnt[nbrs[2*e]], 1);
}

// shfl-based two-level inclusive scan, 1024 threads, 10 chunks
__global__ void k_scan() {
    __shared__ int warp_sums[32];
    __shared__ int carry_s;
    const int tid  = threadIdx.x;
    const int lane = tid & 31, wp = tid >> 5;
    if (tid == 0) carry_s = 0;
    __syncthreads();
    for (int base = 0; base < NA; base += 1024) {
        const int idx = base + tid;
        const int v = (idx < NA) ? g_cnt[idx] : 0;
        int x = v;
        #pragma unroll
        for (int off = 1; off < 32; off <<= 1) {
            int y = __shfl_up_sync(0xFFFFFFFFu, x, off);
            if (lane >= off) x += y;
        }
        if (lane == 31) warp_sums[wp] = x;
        __syncthreads();
        if (wp == 0) {
            int s = warp_sums[lane];
            #pragma unroll
            for (int off = 1; off < 32; off <<= 1) {
                int y = __shfl_up_sync(0xFFFFFFFFu, s, off);
                if (lane >= off) s += y;
            }
            warp_sums[lane] = s;
        }
        __syncthreads();
        const int warp_off = (wp == 0) ? 0 : warp_sums[wp-1];
        const int carry = carry_s;
        const int excl = carry + warp_off + x - v;
        if (idx < NA) { g_roff[idx] = excl; g_cur[idx] = excl; }
        __syncthreads();
        if (tid == 1023) carry_s = carry + warp_sums[31];
        __syncthreads();
    }
    if (tid == 0) g_roff[NA] = carry_s;
}

// ---------------- fused CSR fill + per-edge geometry (Chebyshev rbf) ---------
__global__ void k_fillgeom(const float* __restrict__ xyz, const int* __restrict__ nbrs) {
    int e = blockIdx.x*blockDim.x + threadIdx.x;
    if (e >= NE) return;
    int i = nbrs[2*e], j = nbrs[2*e+1];
    int slot = atomicAdd(&g_cur[i], 1);
    g_sj[slot] = j;
    float dx = xyz[3*j+0] - xyz[3*i+0];
    float dy = xyz[3*j+1] - xyz[3*i+1];
    float dz = xyz[3*j+2] - xyz[3*i+2];
    float d  = sqrtf(dx*dx + dy*dy + dz*dz + EPS_F);
    float inv = 1.0f / d;
    float base = PI_F * d * (1.0f/CUT_R);
    float sb, cb;
    __sincosf(base, &sb, &cb);
    float fc = (d < CUT_R) ? 0.5f*(cb + 1.0f) : 0.0f;
    g_unit[3*slot+0] = dx*inv;
    g_unit[3*slot+1] = dy*inv;
    g_unit[3*slot+2] = dz*inv;
    g_fc[slot] = fc;
    const float sc = inv * fc;
    const float c2 = 2.0f * cb;
    float s_prev = 0.f, s_cur = sb;
    float* rp = g_rbfs + (size_t)slot*NRBF_K;
    #pragma unroll
    for (int k = 0; k < NRBF_K; k++) {
        rp[k] = s_cur * sc;
        const float s_next = fmaf(c2, s_cur, -s_prev);
        s_prev = s_cur;
        s_cur  = s_next;
    }
}

// ---------------- tf32 GEMM, BM=128 BN=64 (proven); optional fp16 output -----
template<bool SILU, bool BIAS, bool HOUT>
__global__ void __launch_bounds__(256) k_tgemm(
        const float* __restrict__ A, const float* __restrict__ B,
        const float* __restrict__ bias, void* __restrict__ Cv,
        int M, int Nn, int K)
{
    __shared__ float As[2][128][20];
    __shared__ float Bs[2][16][68];
    const int t = threadIdx.x;
    const int lane = t & 31, wid = t >> 5;
    const int warp_m = wid & 3;
    const int warp_n = wid >> 2;
    const int row0 = blockIdx.y*128, col0 = blockIdx.x*64;
    const int g = lane >> 2, tg = lane & 3;
    const int ar0 = t >> 2, akq = t & 3;
    const int bk = t >> 4, bn4 = t & 15;

    float acc[2][4][4];
    #pragma unroll
    for (int mt = 0; mt < 2; mt++)
        #pragma unroll
        for (int nt = 0; nt < 4; nt++)
            #pragma unroll
            for (int q = 0; q < 4; q++) acc[mt][nt][q] = 0.f;

    const int NT = K/16;
    {
        #pragma unroll
        for (int u = 0; u < 2; u++) {
            int row = ar0 + u*64;
            int grow = row0 + row;
            float4 v = make_float4(0,0,0,0);
            if (grow < M) v = *(const float4*)(A + (size_t)grow*K + akq*4);
            float4 w = make_float4(totf(v.x), totf(v.y), totf(v.z), totf(v.w));
            *(float4*)&As[0][row][akq*4] = w;
        }
        float4 v = *(const float4*)(B + (size_t)bk*Nn + col0 + bn4*4);
        float4 w = make_float4(totf(v.x), totf(v.y), totf(v.z), totf(v.w));
        *(float4*)&Bs[0][bk][bn4*4] = w;
    }
    __syncthreads();

    for (int kt = 0; kt < NT; kt++) {
        const int buf = kt & 1;
        const bool more = (kt+1 < NT);
        float4 na[2], nb;
        if (more) {
            #pragma unroll
            for (int u = 0; u < 2; u++) {
                int row = ar0 + u*64;
                int grow = row0 + row;
                na[u] = make_float4(0,0,0,0);
                if (grow < M) na[u] = *(const float4*)(A + (size_t)grow*K + (kt+1)*16 + akq*4);
            }
            nb = *(const float4*)(B + (size_t)((kt+1)*16 + bk)*Nn + col0 + bn4*4);
        }
        #pragma unroll
        for (int ks = 0; ks < 2; ks++) {
            const int k0 = ks*8;
            uint32_t a[2][4], b[4][2];
            #pragma unroll
            for (int mt = 0; mt < 2; mt++) {
                const int arow = warp_m*32 + mt*16 + g;
                a[mt][0] = __float_as_uint(As[buf][arow    ][k0 + tg]);
                a[mt][1] = __float_as_uint(As[buf][arow + 8][k0 + tg]);
                a[mt][2] = __float_as_uint(As[buf][arow    ][k0 + tg + 4]);
                a[mt][3] = __float_as_uint(As[buf][arow + 8][k0 + tg + 4]);
            }
            #pragma unroll
            for (int nt = 0; nt < 4; nt++) {
                const int bcol = warp_n*32 + nt*8 + g;
                b[nt][0] = __float_as_uint(Bs[buf][k0 + tg    ][bcol]);
                b[nt][1] = __float_as_uint(Bs[buf][k0 + tg + 4][bcol]);
            }
            #pragma unroll
            for (int mt = 0; mt < 2; mt++)
                #pragma unroll
                for (int nt = 0; nt < 4; nt++)
                    asm volatile(
                        "mma.sync.aligned.m16n8k8.row.col.f32.tf32.tf32.f32 "
                        "{%0,%1,%2,%3}, {%4,%5,%6,%7}, {%8,%9}, {%0,%1,%2,%3};"
                        : "+f"(acc[mt][nt][0]), "+f"(acc[mt][nt][1]),
                          "+f"(acc[mt][nt][2]), "+f"(acc[mt][nt][3])
                        : "r"(a[mt][0]), "r"(a[mt][1]), "r"(a[mt][2]), "r"(a[mt][3]),
                          "r"(b[nt][0]), "r"(b[nt][1]));
        }
        if (more) {
            const int nbuf = buf ^ 1;
            #pragma unroll
            for (int u = 0; u < 2; u++) {
                int row = ar0 + u*64;
                float4 w = make_float4(totf(na[u].x), totf(na[u].y), totf(na[u].z), totf(na[u].w));
                *(float4*)&As[nbuf][row][akq*4] = w;
            }
            float4 w = make_float4(totf(nb.x), totf(nb.y), totf(nb.z), totf(nb.w));
            *(float4*)&Bs[nbuf][bk][bn4*4] = w;
        }
        __syncthreads();
    }

    #pragma unroll
    for (int mt = 0; mt < 2; mt++) {
        #pragma unroll
        for (int nt = 0; nt < 4; nt++) {
            const int c = col0 + warp_n*32 + nt*8 + 2*tg;
            float bb0 = 0.f, bb1 = 0.f;
            if (BIAS) { bb0 = bias[c]; bb1 = bias[c+1]; }
            #pragma unroll
            for (int half = 0; half < 2; half++) {
                const int r = row0 + warp_m*32 + mt*16 + g + half*8;
                if (r >= M) continue;
                float o0 = acc[mt][nt][half*2+0] + bb0;
                float o1 = acc[mt][nt][half*2+1] + bb1;
                if (SILU) {
                    o0 = o0 / (1.0f + __expf(-o0));
                    o1 = o1 / (1.0f + __expf(-o1));
                }
                if (HOUT) {
                    __half2* Ch = (__half2*)Cv;
                    Ch[((size_t)r*Nn + c) >> 1] = __floats2half2_rn(o0, o1);
                } else {
                    *(float2*)((float*)Cv + (size_t)r*Nn + c) = make_float2(o0, o1);
                }
            }
        }
    }
}

// ---------------- cat-GEMM: A built on the fly (s2 | vnorm(uvvv)) ------------
__device__ __forceinline__ float4 loadA_cat(const float* __restrict__ s2,
                                            const float* __restrict__ uvvv,
                                            int n, int gk) {
    if (gk < 128) return *(const float4*)(s2 + (size_t)n*FDIM + gk);
    const int g2 = gk - 128;
    float4 q0 = *(const float4*)(uvvv + ((size_t)(0*NA + n))*256 + 128 + g2);
    float4 q1 = *(const float4*)(uvvv + ((size_t)(1*NA + n))*256 + 128 + g2);
    float4 q2 = *(const float4*)(uvvv + ((size_t)(2*NA + n))*256 + 128 + g2);
    return make_float4(sqrtf(q0.x*q0.x + q1.x*q1.x + q2.x*q2.x + EPS_F),
                       sqrtf(q0.y*q0.y + q1.y*q1.y + q2.y*q2.y + EPS_F),
                       sqrtf(q0.z*q0.z + q1.z*q1.z + q2.z*q2.z + EPS_F),
                       sqrtf(q0.w*q0.w + q1.w*q1.w + q2.w*q2.w + EPS_F));
}

__global__ void __launch_bounds__(256) k_tgemm_cat(
        const float* __restrict__ s2, const float* __restrict__ uvvv,
        const float* __restrict__ B,
        const float* __restrict__ bias, float* __restrict__ C,
        int M, int Nn)
{
    const int K = 256;
    __shared__ float As[2][128][20];
    __shared__ float Bs[2][16][68];
    const int t = threadIdx.x;
    const int lane = t & 31, wid = t >> 5;
    const int warp_m = wid & 3;
    const int warp_n = wid >> 2;
    const int row0 = blockIdx.y*128, col0 = blockIdx.x*64;
    const int g = lane >> 2, tg = lane & 3;
    const int ar0 = t >> 2, akq = t & 3;
    const int bk = t >> 4, bn4 = t & 15;

    float acc[2][4][4];
    #pragma unroll
    for (int mt = 0; mt < 2; mt++)
        #pragma unroll
        for (int nt = 0; nt < 4; nt++)
            #pragma unroll
            for (int q = 0; q < 4; q++) acc[mt][nt][q] = 0.f;

    const int NT = K/16;   // 16
    {
        #pragma unroll
        for (int u = 0; u < 2; u++) {
            int row = ar0 + u*64;
            int grow = row0 + row;
            float4 v = make_float4(0,0,0,0);
            if (grow < M) v = loadA_cat(s2, uvvv, grow, akq*4);
            float4 w = make_float4(totf(v.x), totf(v.y), totf(v.z), totf(v.w));
            *(float4*)&As[0][row][akq*4] = w;
        }
        float4 v = *(const float4*)(B + (size_t)bk*Nn + col0 + bn4*4);
        float4 w = make_float4(totf(v.x), totf(v.y), totf(v.z), totf(v.w));
        *(float4*)&Bs[0][bk][bn4*4] = w;
    }
    __syncthreads();

    for (int kt = 0; kt < NT; kt++) {
        const int buf = kt & 1;
        const bool more = (kt+1 < NT);
        float4 na[2], nb;
        if (more) {
            #pragma unroll
            for (int u = 0; u < 2; u++) {
                int row = ar0 + u*64;
                int grow = row0 + row;
                na[u] = make_float4(0,0,0,0);
                if (grow < M) na[u] = loadA_cat(s2, uvvv, grow, (kt+1)*16 + akq*4);
            }
            nb = *(const float4*)(B + (size_t)((kt+1)*16 + bk)*Nn + col0 + bn4*4);
        }
        #pragma unroll
        for (int ks = 0; ks < 2; ks++) {
            const int k0 = ks*8;
            uint32_t a[2][4], b[4][2];
            #pragma unroll
            for (int mt = 0; mt < 2; mt++) {
                const int arow = warp_m*32 + mt*16 + g;
                a[mt][0] = __float_as_uint(As[buf][arow    ][k0 + tg]);
                a[mt][1] = __float_as_uint(As[buf][arow + 8][k0 + tg]);
                a[mt][2] = __float_as_uint(As[buf][arow    ][k0 + tg + 4]);
                a[mt][3] = __float_as_uint(As[buf][arow + 8][k0 + tg + 4]);
            }
            #pragma unroll
            for (int nt = 0; nt < 4; nt++) {
                const int bcol = warp_n*32 + nt*8 + g;
                b[nt][0] = __float_as_uint(Bs[buf][k0 + tg    ][bcol]);
                b[nt][1] = __float_as_uint(Bs[buf][k0 + tg + 4][bcol]);
            }
            #pragma unroll
            for (int mt = 0; mt < 2; mt++)
                #pragma unroll
                for (int nt = 0; nt < 4; nt++)
                    asm volatile(
                        "mma.sync.aligned.m16n8k8.row.col.f32.tf32.tf32.f32 "
                        "{%0,%1,%2,%3}, {%4,%5,%6,%7}, {%8,%9}, {%0,%1,%2,%3};"
                        : "+f"(acc[mt][nt][0]), "+f"(acc[mt][nt][1]),
                          "+f"(acc[mt][nt][2]), "+f"(acc[mt][nt][3])
                        : "r"(a[mt][0]), "r"(a[mt][1]), "r"(a[mt][2]), "r"(a[mt][3]),
                          "r"(b[nt][0]), "r"(b[nt][1]));
        }
        if (more) {
            const int nbuf = buf ^ 1;
            #pragma unroll
            for (int u = 0; u < 2; u++) {
                int row = ar0 + u*64;
                float4 w = make_float4(totf(na[u].x), totf(na[u].y), totf(na[u].z), totf(na[u].w));
                *(float4*)&As[nbuf][row][akq*4] = w;
            }
            float4 w = make_float4(totf(nb.x), totf(nb.y), totf(nb.z), totf(nb.w));
            *(float4*)&Bs[nbuf][bk][bn4*4] = w;
        }
        __syncthreads();
    }

    #pragma unroll
    for (int mt = 0; mt < 2; mt++) {
        #pragma unroll
        for (int nt = 0; nt < 4; nt++) {
            const int c = col0 + warp_n*32 + nt*8 + 2*tg;
            float bb0 = bias[c], bb1 = bias[c+1];
            #pragma unroll
            for (int half = 0; half < 2; half++) {
                const int r = row0 + warp_m*32 + mt*16 + g + half*8;
                if (r >= M) continue;
                float o0 = acc[mt][nt][half*2+0] + bb0;
                float o1 = acc[mt][nt][half*2+1] + bb1;
                o0 = o0 / (1.0f + __expf(-o0));
                o1 = o1 / (1.0f + __expf(-o1));
                *(float2*)(C + (size_t)r*Nn + c) = make_float2(o0, o1);
            }
        }
    }
}

// ---------------- CSR edge kernel (FFMA form; fp16 gathers) ------------------
__global__ void __launch_bounds__(128) k_edge(
        const float*  __restrict__ dW,     // [20][384]
        const float*  __restrict__ db,     // [384]
        const __half* __restrict__ phi,    // [N][384] fp16
        const float*  __restrict__ s1,
        const float*  __restrict__ v1,     // [3][N][128] fp32 (aligned reads)
        const __half* __restrict__ v1h,    // [3][N][128] fp16 (gathers)
        float* __restrict__ s2,
        float* __restrict__ v2)
{
    const int i = blockIdx.x, f = threadIdx.x;
    __shared__ float s_rbf [32*NRBF_K];
    __shared__ float s_unit[32*3];
    __shared__ float s_fc  [32];
    __shared__ int   s_jj  [32];

    float wA[NRBF_K], wB[NRBF_K], wC[NRBF_K];
    #pragma unroll
    for (int k = 0; k < NRBF_K; k++) {
        wA[k] = dW[k*PHI_D + f];
        wB[k] = dW[k*PHI_D + 128 + f];
        wC[k] = dW[k*PHI_D + 256 + f];
    }
    const float bA = db[f], bB = db[128+f], bC = db[256+f];
    const int r0 = g_roff[i], r1 = g_roff[i+1];

    float accS = 0.f, aV0 = 0.f, aV1 = 0.f, aV2 = 0.f;
    for (int base = r0; base < r1; base += 32) {
        const int cnt = min(32, r1 - base);
        __syncthreads();
        for (int idx = f; idx < cnt*NRBF_K; idx += 128) s_rbf[idx]  = g_rbfs[(size_t)base*NRBF_K + idx];
        for (int idx = f; idx < cnt*3;      idx += 128) s_unit[idx] = g_unit[(size_t)base*3 + idx];
        if (f < cnt) { s_fc[f] = g_fc[base+f]; s_jj[f] = g_sj[base+f]; }
        __syncthreads();
        for (int t = 0; t < cnt; t++) {
            const float fcv = s_fc[t];
            float w0 = fcv*bA, w1 = fcv*bB, w2 = fcv*bC;
            #pragma unroll
            for (int k = 0; k < NRBF_K; k++) {
                const float r = s_rbf[t*NRBF_K + k];
                w0 = fmaf(r, wA[k], w0);
                w1 = fmaf(r, wB[k], w1);
                w2 = fmaf(r, wC[k], w2);
            }
            const int j = s_jj[t];
            const __half* pj = phi + (size_t)j*PHI_D;
            const float i0 = __half2float(pj[f])*w0;
            const float i1 = __half2float(pj[128+f])*w1;
            const float i2 = __half2float(pj[256+f])*w2;
            accS += i0;
            const __half* vj = v1h + (size_t)j*FDIM + f;
            aV0 = fmaf(i1, __half2float(vj[0]),    fmaf(i2, s_unit[t*3+0], aV0));
            aV1 = fmaf(i1, __half2float(vj[NF]),   fmaf(i2, s_unit[t*3+1], aV1));
            aV2 = fmaf(i1, __half2float(vj[2*NF]), fmaf(i2, s_unit[t*3+2], aV2));
        }
    }
    const size_t o = (size_t)i*FDIM + f;
    s2[o]          = s1[o]          + accS;
    v2[o]          = v1[o]          + aV0;
    v2[o + NF]     = v1[o + NF]     + aV1;
    v2[o + 2*NF]   = v1[o + 2*NF]   + aV2;
}

// ---------------- combine (also refreshes fp16 v shadow) ---------------------
__global__ void k_combine(const float* __restrict__ s2, const float* __restrict__ v2,
                          const float* __restrict__ uvvv, const float* __restrict__ aw,
                          float* __restrict__ sOut, float* __restrict__ vOut,
                          __half* __restrict__ vOutH) {
    int idx = blockIdx.x*blockDim.x + threadIdx.x;
    if (idx >= NF) return;
    int n = idx >> 7, f = idx & 127;
    float a0 = aw[(size_t)n*PHI_D + f];
    float a1 = aw[(size_t)n*PHI_D + 128 + f];
    float a2 = aw[(size_t)n*PHI_D + 256 + f];
    float u0 = uvvv[((size_t)(0*NA+n))*256 + f];
    float u1 = uvvv[((size_t)(1*NA+n))*256 + f];
    float u2 = uvvv[((size_t)(2*NA+n))*256 + f];
    float w0 = uvvv[((size_t)(0*NA+n))*256 + 128 + f];
    float w1 = uvvv[((size_t)(1*NA+n))*256 + 128 + f];
    float w2 = uvvv[((size_t)(2*NA+n))*256 + 128 + f];
    float dot = u0*w0 + u1*w1 + u2*w2;
    sOut[idx] = s2[idx] + a1*dot + a2;
    float vo0 = v2[idx]        + u0*a0;
    float vo1 = v2[idx + NF]   + u1*a0;
    float vo2 = v2[idx + 2*NF] + u2*a0;
    vOut[idx]        = vo0;
    vOut[idx + NF]   = vo1;
    vOut[idx + 2*NF] = vo2;
    vOutH[idx]        = __float2half(vo0);
    vOutH[idx + NF]   = __float2half(vo1);
    vOutH[idx + 2*NF] = __float2half(vo2);
}

// ---------------- readout ----------------------------------------------------
__global__ void k_readout(const float* __restrict__ hid, const float* __restrict__ W2,
                          const float* __restrict__ b2, const int* __restrict__ mol,
                          float* __restrict__ out) {
    int n = blockIdx.x*blockDim.x + threadIdx.x;
    if (n >= NA) return;
    float acc = b2[0];
    const float* h = hid + (size_t)n*64;
    #pragma unroll
    for (int k = 0; k < 64; k++) acc = fmaf(h[k], W2[k], acc);
    atomicAdd(&out[mol[n]], acc);
}

// ---------------- host-side orchestration ------------------------------------
extern "C" void kernel_launch(void* const* d_in, const int* in_sizes, int n_in,
                              void* d_out, int out_size) {
    const float* xyz    = (const float*)d_in[0];
    const int*   z      = (const int*)  d_in[1];
    const int*   nbrs   = (const int*)  d_in[2];
    const int*   mol    = (const int*)  d_in[3];
    const float* emb    = (const float*)d_in[4];
    const float* msgW1  = (const float*)d_in[5];
    const float* msgb1  = (const float*)d_in[6];
    const float* msgW2  = (const float*)d_in[7];
    const float* msgb2  = (const float*)d_in[8];
    const float* distW  = (const float*)d_in[9];
    const float* distb  = (const float*)d_in[10];
    const float* updU   = (const float*)d_in[11];
    const float* updV   = (const float*)d_in[12];
    const float* updW1  = (const float*)d_in[13];
    const float* updb1  = (const float*)d_in[14];
    const float* updW2  = (const float*)d_in[15];
    const float* updb2  = (const float*)d_in[16];
    const float* readW1 = (const float*)d_in[17];
    const float* readb1 = (const float*)d_in[18];
    const float* readW2 = (const float*)d_in[19];
    const float* readb2 = (const float*)d_in[20];
    float* out = (float*)d_out;

    float *s1, *s2, *v1, *v2, *hid, *uvvv, *aw, *Bcat;
    __half *phih, *v1h;
    cudaGetSymbolAddress((void**)&s1,    g_s1);
    cudaGetSymbolAddress((void**)&s2,    g_s2);
    cudaGetSymbolAddress((void**)&v1,    g_v1);
    cudaGetSymbolAddress((void**)&v2,    g_v2);
    cudaGetSymbolAddress((void**)&phih,  g_phih);
    cudaGetSymbolAddress((void**)&v1h,   g_v1h);
    cudaGetSymbolAddress((void**)&hid,   g_hid);
    cudaGetSymbolAddress((void**)&uvvv,  g_uvvv);
    cudaGetSymbolAddress((void**)&aw,    g_aw);
    cudaGetSymbolAddress((void**)&Bcat,  g_Bcat);

    const int TPB = 256;
    const int GY1 = (NA + 127)/128;       // 79
    const int GY3 = (3*NA + 127)/128;     // 235

    // prep; launch #4 = gemm1 (clock probe)
    k_prep0<<<NF/TPB, TPB>>>(emb, z, updU, updV);                    // 1
    k_count<<<NE/TPB, TPB>>>(nbrs);                                  // 2
    k_scan <<<1, 1024>>>();                                          // 3
    k_tgemm<true, true, false><<<dim3(2, GY1), 256>>>(s1, msgW1, msgb1, hid, NA, 128, 128); // 4 (probe)
    k_fillgeom<<<NE/TPB, TPB>>>(xyz, nbrs);                          // 5

    for (int l = 0; l < NLAYERS; l++) {
        const float* mW1 = msgW1 + (size_t)l*128*128;
        const float* mb1 = msgb1 + (size_t)l*128;
        const float* mW2 = msgW2 + (size_t)l*128*384;
        const float* mb2 = msgb2 + (size_t)l*384;
        const float* dW  = distW + (size_t)l*NRBF_K*384;
        const float* dbv = distb + (size_t)l*384;
        const float* uW1 = updW1 + (size_t)l*256*128;
        const float* ub1 = updb1 + (size_t)l*128;
        const float* uW2 = updW2 + (size_t)l*128*384;
        const float* ub2 = updb2 + (size_t)l*384;
        const float* Bc  = Bcat  + (size_t)l*128*256;

        if (l > 0)
            k_tgemm<true, true, false><<<dim3(2, GY1), 256>>>(s1, mW1, mb1, hid, NA, 128, 128);
        // phi GEMM writes fp16 directly
        k_tgemm<false, true, true><<<dim3(6, GY1), 256>>>(hid, mW2, mb2, phih, NA, 384, 128);
        // edge aggregation (CSR, FFMA, fp16 gathers)
        k_edge<<<NA, 128>>>(dW, dbv, phih, s1, v1, v1h, s2, v2);
        // update phase: [uv | vv] in one GEMM (N=256)
        k_tgemm<false, false, false><<<dim3(4, GY3), 256>>>(v2, Bc, (const float*)nullptr, uvvv, 3*NA, 256, 128);
        // cat-GEMM with on-the-fly A = [s2 | vnorm(uvvv)]
        k_tgemm_cat<<<dim3(2, GY1), 256>>>(s2, uvvv, uW1, ub1, hid, NA, 128);
        k_tgemm<false, true, false><<<dim3(6, GY1), 256>>>(hid, uW2, ub2, aw,  NA, 384, 128);
        k_combine<<<NF/TPB, TPB>>>(s2, v2, uvvv, aw, s1, v1, v1h);
    }

    // readout
    k_tgemm<true, true, false><<<dim3(1, GY1), 256>>>(s1, readW1, readb1, hid, NA, 64, 128);
    cudaMemsetAsync(out, 0, NMOLS*sizeof(float));
    k_readout<<<(NA + TPB-1)/TPB, TPB>>>(hid, readW2, readb2, mol, out);
}

// round 17
// speedup vs baseline: 1.4465x; 1.4465x over previous
#include <cuda_runtime.h>
#include <cuda_fp16.h>
#include <math.h>
#include <stdint.h>

#define NA      10000
#define NE      256000
#define FDIM    128
#define NRBF_K  20
#define NLAYERS 3
#define NMOLS   100
#define NF      (NA*FDIM)               // 1,280,000
#define PHI_D   384
#define CUT_R   5.0f
#define EPS_F   1e-8f
#define PI_F    3.14159265358979323846f

// ---------------- scratch (device globals; no allocations allowed) ----------
__device__ float  g_rbfs[NE*NRBF_K];    // rbf * fcut, CSR-sorted (live edges only)
__device__ float  g_unit[NE*3];         // CSR-sorted
__device__ float  g_fc  [NE];           // fcut, CSR-sorted
__device__ int    g_sj  [NE];           // j per CSR slot
__device__ int    g_cnt [NA];
__device__ int    g_roff[NA+1];
__device__ int    g_cur [NA];
__device__ float  g_s1  [NF];
__device__ float  g_s2  [NF];
__device__ float  g_v1  [3*NF];
__device__ float  g_v2  [3*NF];
__device__ __half g_phih[NA*PHI_D];     // phi in fp16 (gather copy)
__device__ __half g_v1h [3*NF];         // v1 in fp16 (gather copy)
__device__ float  g_hid [NF];
__device__ float  g_uvvv[(size_t)3*NA*256];
__device__ float  g_aw  [NA*PHI_D];
__device__ float  g_Bcat[NLAYERS*FDIM*256];  // [l][k][ U | V ]

__device__ __forceinline__ float totf(float x) {
    float r; asm("cvt.rna.tf32.f32 %0, %1;" : "=f"(r) : "f"(x)); return r;
}

// edge distance (must be the SAME formula in count & fill for a consistent CSR)
__device__ __forceinline__ float edge_dist(const float* __restrict__ xyz, int i, int j) {
    float dx = xyz[3*j+0] - xyz[3*i+0];
    float dy = xyz[3*j+1] - xyz[3*i+1];
    float dz = xyz[3*j+2] - xyz[3*i+2];
    return sqrtf(dx*dx + dy*dy + dz*dz + EPS_F);
}

// ---------------- fused prep: s/v init, cnt zero, Bcat -----------------------
__global__ void k_prep0(const float* __restrict__ emb, const int* __restrict__ z,
                        const float* __restrict__ U, const float* __restrict__ V) {
    int idx = blockIdx.x*blockDim.x + threadIdx.x;
    if (idx < NF) {
        int n = idx >> 7, ff = idx & 127;
        g_s1[idx] = emb[z[n]*FDIM + ff];
        g_v1[idx] = 0.f; g_v1[idx + NF] = 0.f; g_v1[idx + 2*NF] = 0.f;
        const __half hz = __float2half(0.f);
        g_v1h[idx] = hz; g_v1h[idx + NF] = hz; g_v1h[idx + 2*NF] = hz;
    }
    if (idx < NA) g_cnt[idx] = 0;
    if (idx < NLAYERS*FDIM*256) {
        int l = idx >> 15, rem = idx & 32767, k = rem >> 8, gg = rem & 255;
        g_Bcat[idx] = (gg < 128) ? U[l*16384 + k*128 + gg] : V[l*16384 + k*128 + gg - 128];
    }
}

// ---------------- CSR build: LIVE edges only (d < CUT_R) ---------------------
// Edges with d >= CUT_R have fcut = 0 => ds_edge = dv_edge = 0 exactly; drop them.
__global__ void k_count(const float* __restrict__ xyz, const int* __restrict__ nbrs) {
    int e = blockIdx.x*blockDim.x + threadIdx.x;
    if (e >= NE) return;
    int i = nbrs[2*e], j = nbrs[2*e+1];
    if (edge_dist(xyz, i, j) < CUT_R) atomicAdd(&g_cnt[i], 1);
}

// shfl-based two-level inclusive scan, 1024 threads, 10 chunks
__global__ void k_scan() {
    __shared__ int warp_sums[32];
    __shared__ int carry_s;
    const int tid  = threadIdx.x;
    const int lane = tid & 31, wp = tid >> 5;
    if (tid == 0) carry_s = 0;
    __syncthreads();
    for (int base = 0; base < NA; base += 1024) {
        const int idx = base + tid;
        const int v = (idx < NA) ? g_cnt[idx] : 0;
        int x = v;
        #pragma unroll
        for (int off = 1; off < 32; off <<= 1) {
            int y = __shfl_up_sync(0xFFFFFFFFu, x, off);
            if (lane >= off) x += y;
        }
        if (lane == 31) warp_sums[wp] = x;
        __syncthreads();
        if (wp == 0) {
            int s = warp_sums[lane];
            #pragma unroll
            for (int off = 1; off < 32; off <<= 1) {
                int y = __shfl_up_sync(0xFFFFFFFFu, s, off);
                if (lane >= off) s += y;
            }
            warp_sums[lane] = s;
        }
        __syncthreads();
        const int warp_off = (wp == 0) ? 0 : warp_sums[wp-1];
        const int carry = carry_s;
        const int excl = carry + warp_off + x - v;
        if (idx < NA) { g_roff[idx] = excl; g_cur[idx] = excl; }
        __syncthreads();
        if (tid == 1023) carry_s = carry + warp_sums[31];
        __syncthreads();
    }
    if (tid == 0) g_roff[NA] = carry_s;
}

// ---------------- fused CSR fill + per-edge geometry (live edges only) -------
__global__ void k_fillgeom(const float* __restrict__ xyz, const int* __restrict__ nbrs) {
    int e = blockIdx.x*blockDim.x + threadIdx.x;
    if (e >= NE) return;
    int i = nbrs[2*e], j = nbrs[2*e+1];
    float d = edge_dist(xyz, i, j);
    if (!(d < CUT_R)) return;                 // dead edge: exact-zero contribution
    int slot = atomicAdd(&g_cur[i], 1);
    g_sj[slot] = j;
    float dx = xyz[3*j+0] - xyz[3*i+0];
    float dy = xyz[3*j+1] - xyz[3*i+1];
    float dz = xyz[3*j+2] - xyz[3*i+2];
    float inv = 1.0f / d;
    float base = PI_F * d * (1.0f/CUT_R);
    float sb, cb;
    __sincosf(base, &sb, &cb);
    float fc = 0.5f*(cb + 1.0f);
    g_unit[3*slot+0] = dx*inv;
    g_unit[3*slot+1] = dy*inv;
    g_unit[3*slot+2] = dz*inv;
    g_fc[slot] = fc;
    const float sc = inv * fc;
    const float c2 = 2.0f * cb;
    float s_prev = 0.f, s_cur = sb;
    float* rp = g_rbfs + (size_t)slot*NRBF_K;
    #pragma unroll
    for (int k = 0; k < NRBF_K; k++) {
        rp[k] = s_cur * sc;
        const float s_next = fmaf(c2, s_cur, -s_prev);
        s_prev = s_cur;
        s_cur  = s_next;
    }
}

// ---------------- tf32 GEMM, BM=128 BN=64 (proven); optional fp16 output -----
template<bool SILU, bool BIAS, bool HOUT>
__global__ void __launch_bounds__(256) k_tgemm(
        const float* __restrict__ A, const float* __restrict__ B,
        const float* __restrict__ bias, void* __restrict__ Cv,
        int M, int Nn, int K)
{
    __shared__ float As[2][128][20];
    __shared__ float Bs[2][16][68];
    const int t = threadIdx.x;
    const int lane = t & 31, wid = t >> 5;
    const int warp_m = wid & 3;
    const int warp_n = wid >> 2;
    const int row0 = blockIdx.y*128, col0 = blockIdx.x*64;
    const int g = lane >> 2, tg = lane & 3;
    const int ar0 = t >> 2, akq = t & 3;
    const int bk = t >> 4, bn4 = t & 15;

    float acc[2][4][4];
    #pragma unroll
    for (int mt = 0; mt < 2; mt++)
        #pragma unroll
        for (int nt = 0; nt < 4; nt++)
            #pragma unroll
            for (int q = 0; q < 4; q++) acc[mt][nt][q] = 0.f;

    const int NT = K/16;
    {
        #pragma unroll
        for (int u = 0; u < 2; u++) {
            int row = ar0 + u*64;
            int grow = row0 + row;
            float4 v = make_float4(0,0,0,0);
            if (grow < M) v = *(const float4*)(A + (size_t)grow*K + akq*4);
            float4 w = make_float4(totf(v.x), totf(v.y), totf(v.z), totf(v.w));
            *(float4*)&As[0][row][akq*4] = w;
        }
        float4 v = *(const float4*)(B + (size_t)bk*Nn + col0 + bn4*4);
        float4 w = make_float4(totf(v.x), totf(v.y), totf(v.z), totf(v.w));
        *(float4*)&Bs[0][bk][bn4*4] = w;
    }
    __syncthreads();

    for (int kt = 0; kt < NT; kt++) {
        const int buf = kt & 1;
        const bool more = (kt+1 < NT);
        float4 na[2], nb;
        if (more) {
            #pragma unroll
            for (int u = 0; u < 2; u++) {
                int row = ar0 + u*64;
                int grow = row0 + row;
                na[u] = make_float4(0,0,0,0);
                if (grow < M) na[u] = *(const float4*)(A + (size_t)grow*K + (kt+1)*16 + akq*4);
            }
            nb = *(const float4*)(B + (size_t)((kt+1)*16 + bk)*Nn + col0 + bn4*4);
        }
        #pragma unroll
        for (int ks = 0; ks < 2; ks++) {
            const int k0 = ks*8;
            uint32_t a[2][4], b[4][2];
            #pragma unroll
            for (int mt = 0; mt < 2; mt++) {
                const int arow = warp_m*32 + mt*16 + g;
                a[mt][0] = __float_as_uint(As[buf][arow    ][k0 + tg]);
                a[mt][1] = __float_as_uint(As[buf][arow + 8][k0 + tg]);
                a[mt][2] = __float_as_uint(As[buf][arow    ][k0 + tg + 4]);
                a[mt][3] = __float_as_uint(As[buf][arow + 8][k0 + tg + 4]);
            }
            #pragma unroll
            for (int nt = 0; nt < 4; nt++) {
                const int bcol = warp_n*32 + nt*8 + g;
                b[nt][0] = __float_as_uint(Bs[buf][k0 + tg    ][bcol]);
                b[nt][1] = __float_as_uint(Bs[buf][k0 + tg + 4][bcol]);
            }
            #pragma unroll
            for (int mt = 0; mt < 2; mt++)
                #pragma unroll
                for (int nt = 0; nt < 4; nt++)
                    asm volatile(
                        "mma.sync.aligned.m16n8k8.row.col.f32.tf32.tf32.f32 "
                        "{%0,%1,%2,%3}, {%4,%5,%6,%7}, {%8,%9}, {%0,%1,%2,%3};"
                        : "+f"(acc[mt][nt][0]), "+f"(acc[mt][nt][1]),
                          "+f"(acc[mt][nt][2]), "+f"(acc[mt][nt][3])
                        : "r"(a[mt][0]), "r"(a[mt][1]), "r"(a[mt][2]), "r"(a[mt][3]),
                          "r"(b[nt][0]), "r"(b[nt][1]));
        }
        if (more) {
            const int nbuf = buf ^ 1;
            #pragma unroll
            for (int u = 0; u < 2; u++) {
                int row = ar0 + u*64;
                float4 w = make_float4(totf(na[u].x), totf(na[u].y), totf(na[u].z), totf(na[u].w));
                *(float4*)&As[nbuf][row][akq*4] = w;
            }
            float4 w = make_float4(totf(nb.x), totf(nb.y), totf(nb.z), totf(nb.w));
            *(float4*)&Bs[nbuf][bk][bn4*4] = w;
        }
        __syncthreads();
    }

    #pragma unroll
    for (int mt = 0; mt < 2; mt++) {
        #pragma unroll
        for (int nt = 0; nt < 4; nt++) {
            const int c = col0 + warp_n*32 + nt*8 + 2*tg;
            float bb0 = 0.f, bb1 = 0.f;
            if (BIAS) { bb0 = bias[c]; bb1 = bias[c+1]; }
            #pragma unroll
            for (int half = 0; half < 2; half++) {
                const int r = row0 + warp_m*32 + mt*16 + g + half*8;
                if (r >= M) continue;
                float o0 = acc[mt][nt][half*2+0] + bb0;
                float o1 = acc[mt][nt][half*2+1] + bb1;
                if (SILU) {
                    o0 = o0 / (1.0f + __expf(-o0));
                    o1 = o1 / (1.0f + __expf(-o1));
                }
                if (HOUT) {
                    __half2* Ch = (__half2*)Cv;
                    Ch[((size_t)r*Nn + c) >> 1] = __floats2half2_rn(o0, o1);
                } else {
                    *(float2*)((float*)Cv + (size_t)r*Nn + c) = make_float2(o0, o1);
                }
            }
        }
    }
}

// ---------------- cat-GEMM: A built on the fly (s2 | vnorm(uvvv)) ------------
__device__ __forceinline__ float4 loadA_cat(const float* __restrict__ s2,
                                            const float* __restrict__ uvvv,
                                            int n, int gk) {
    if (gk < 128) return *(const float4*)(s2 + (size_t)n*FDIM + gk);
    const int g2 = gk - 128;
    float4 q0 = *(const float4*)(uvvv + ((size_t)(0*NA + n))*256 + 128 + g2);
    float4 q1 = *(const float4*)(uvvv + ((size_t)(1*NA + n))*256 + 128 + g2);
    float4 q2 = *(const float4*)(uvvv + ((size_t)(2*NA + n))*256 + 128 + g2);
    return make_float4(sqrtf(q0.x*q0.x + q1.x*q1.x + q2.x*q2.x + EPS_F),
                       sqrtf(q0.y*q0.y + q1.y*q1.y + q2.y*q2.y + EPS_F),
                       sqrtf(q0.z*q0.z + q1.z*q1.z + q2.z*q2.z + EPS_F),
                       sqrtf(q0.w*q0.w + q1.w*q1.w + q2.w*q2.w + EPS_F));
}

__global__ void __launch_bounds__(256) k_tgemm_cat(
        const float* __restrict__ s2, const float* __restrict__ uvvv,
        const float* __restrict__ B,
        const float* __restrict__ bias, float* __restrict__ C,
        int M, int Nn)
{
    const int K = 256;
    __shared__ float As[2][128][20];
    __shared__ float Bs[2][16][68];
    const int t = threadIdx.x;
    const int lane = t & 31, wid = t >> 5;
    const int warp_m = wid & 3;
    const int warp_n = wid >> 2;
    const int row0 = blockIdx.y*128, col0 = blockIdx.x*64;
    const int g = lane >> 2, tg = lane & 3;
    const int ar0 = t >> 2, akq = t & 3;
    const int bk = t >> 4, bn4 = t & 15;

    float acc[2][4][4];
    #pragma unroll
    for (int mt = 0; mt < 2; mt++)
        #pragma unroll
        for (int nt = 0; nt < 4; nt++)
            #pragma unroll
            for (int q = 0; q < 4; q++) acc[mt][nt][q] = 0.f;

    const int NT = K/16;   // 16
    {
        #pragma unroll
        for (int u = 0; u < 2; u++) {
            int row = ar0 + u*64;
            int grow = row0 + row;
            float4 v = make_float4(0,0,0,0);
            if (grow < M) v = loadA_cat(s2, uvvv, grow, akq*4);
            float4 w = make_float4(totf(v.x), totf(v.y), totf(v.z), totf(v.w));
            *(float4*)&As[0][row][akq*4] = w;
        }
        float4 v = *(const float4*)(B + (size_t)bk*Nn + col0 + bn4*4);
        float4 w = make_float4(totf(v.x), totf(v.y), totf(v.z), totf(v.w));
        *(float4*)&Bs[0][bk][bn4*4] = w;
    }
    __syncthreads();

    for (int kt = 0; kt < NT; kt++) {
        const int buf = kt & 1;
        const bool more = (kt+1 < NT);
        float4 na[2], nb;
        if (more) {
            #pragma unroll
            for (int u = 0; u < 2; u++) {
                int row = ar0 + u*64;
                int grow = row0 + row;
                na[u] = make_float4(0,0,0,0);
                if (grow < M) na[u] = loadA_cat(s2, uvvv, grow, (kt+1)*16 + akq*4);
            }
            nb = *(const float4*)(B + (size_t)((kt+1)*16 + bk)*Nn + col0 + bn4*4);
        }
        #pragma unroll
        for (int ks = 0; ks < 2; ks++) {
            const int k0 = ks*8;
            uint32_t a[2][4], b[4][2];
            #pragma unroll
            for (int mt = 0; mt < 2; mt++) {
                const int arow = warp_m*32 + mt*16 + g;
                a[mt][0] = __float_as_uint(As[buf][arow    ][k0 + tg]);
                a[mt][1] = __float_as_uint(As[buf][arow + 8][k0 + tg]);
                a[mt][2] = __float_as_uint(As[buf][arow    ][k0 + tg + 4]);
                a[mt][3] = __float_as_uint(As[buf][arow + 8][k0 + tg + 4]);
            }
            #pragma unroll
            for (int nt = 0; nt < 4; nt++) {
                const int bcol = warp_n*32 + nt*8 + g;
                b[nt][0] = __float_as_uint(Bs[buf][k0 + tg    ][bcol]);
                b[nt][1] = __float_as_uint(Bs[buf][k0 + tg + 4][bcol]);
            }
            #pragma unroll
            for (int mt = 0; mt < 2; mt++)
                #pragma unroll
                for (int nt = 0; nt < 4; nt++)
                    asm volatile(
                        "mma.sync.aligned.m16n8k8.row.col.f32.tf32.tf32.f32 "
                        "{%0,%1,%2,%3}, {%4,%5,%6,%7}, {%8,%9}, {%0,%1,%2,%3};"
                        : "+f"(acc[mt][nt][0]), "+f"(acc[mt][nt][1]),
                          "+f"(acc[mt][nt][2]), "+f"(acc[mt][nt][3])
                        : "r"(a[mt][0]), "r"(a[mt][1]), "r"(a[mt][2]), "r"(a[mt][3]),
                          "r"(b[nt][0]), "r"(b[nt][1]));
        }
        if (more) {
            const int nbuf = buf ^ 1;
            #pragma unroll
            for (int u = 0; u < 2; u++) {
                int row = ar0 + u*64;
                float4 w = make_float4(totf(na[u].x), totf(na[u].y), totf(na[u].z), totf(na[u].w));
                *(float4*)&As[nbuf][row][akq*4] = w;
            }
            float4 w = make_float4(totf(nb.x), totf(nb.y), totf(nb.z), totf(nb.w));
            *(float4*)&Bs[nbuf][bk][bn4*4] = w;
        }
        __syncthreads();
    }

    #pragma unroll
    for (int mt = 0; mt < 2; mt++) {
        #pragma unroll
        for (int nt = 0; nt < 4; nt++) {
            const int c = col0 + warp_n*32 + nt*8 + 2*tg;
            float bb0 = bias[c], bb1 = bias[c+1];
            #pragma unroll
            for (int half = 0; half < 2; half++) {
                const int r = row0 + warp_m*32 + mt*16 + g + half*8;
                if (r >= M) continue;
                float o0 = acc[mt][nt][half*2+0] + bb0;
                float o1 = acc[mt][nt][half*2+1] + bb1;
                o0 = o0 / (1.0f + __expf(-o0));
                o1 = o1 / (1.0f + __expf(-o1));
                *(float2*)(C + (size_t)r*Nn + c) = make_float2(o0, o1);
            }
        }
    }
}

// ---------------- CSR edge kernel (FFMA form; fp16 gathers) ------------------
__global__ void __launch_bounds__(128) k_edge(
        const float*  __restrict__ dW,     // [20][384]
        const float*  __restrict__ db,     // [384]
        const __half* __restrict__ phi,    // [N][384] fp16
        const float*  __restrict__ s1,
        const float*  __restrict__ v1,     // [3][N][128] fp32 (aligned reads)
        const __half* __restrict__ v1h,    // [3][N][128] fp16 (gathers)
        float* __restrict__ s2,
        float* __restrict__ v2)
{
    const int i = blockIdx.x, f = threadIdx.x;
    __shared__ float s_rbf [32*NRBF_K];
    __shared__ float s_unit[32*3];
    __shared__ float s_fc  [32];
    __shared__ int   s_jj  [32];

    float wA[NRBF_K], wB[NRBF_K], wC[NRBF_K];
    #pragma unroll
    for (int k = 0; k < NRBF_K; k++) {
        wA[k] = dW[k*PHI_D + f];
        wB[k] = dW[k*PHI_D + 128 + f];
        wC[k] = dW[k*PHI_D + 256 + f];
    }
    const float bA = db[f], bB = db[128+f], bC = db[256+f];
    const int r0 = g_roff[i], r1 = g_roff[i+1];

    float accS = 0.f, aV0 = 0.f, aV1 = 0.f, aV2 = 0.f;
    for (int base = r0; base < r1; base += 32) {
        const int cnt = min(32, r1 - base);
        __syncthreads();
        for (int idx = f; idx < cnt*NRBF_K; idx += 128) s_rbf[idx]  = g_rbfs[(size_t)base*NRBF_K + idx];
        for (int idx = f; idx < cnt*3;      idx += 128) s_unit[idx] = g_unit[(size_t)base*3 + idx];
        if (f < cnt) { s_fc[f] = g_fc[base+f]; s_jj[f] = g_sj[base+f]; }
        __syncthreads();
        for (int t = 0; t < cnt; t++) {
            const float fcv = s_fc[t];
            float w0 = fcv*bA, w1 = fcv*bB, w2 = fcv*bC;
            #pragma unroll
            for (int k = 0; k < NRBF_K; k++) {
                const float r = s_rbf[t*NRBF_K + k];
                w0 = fmaf(r, wA[k], w0);
                w1 = fmaf(r, wB[k], w1);
                w2 = fmaf(r, wC[k], w2);
            }
            const int j = s_jj[t];
            const __half* pj = phi + (size_t)j*PHI_D;
            const float i0 = __half2float(pj[f])*w0;
            const float i1 = __half2float(pj[128+f])*w1;
            const float i2 = __half2float(pj[256+f])*w2;
            accS += i0;
            const __half* vj = v1h + (size_t)j*FDIM + f;
            aV0 = fmaf(i1, __half2float(vj[0]),    fmaf(i2, s_unit[t*3+0], aV0));
            aV1 = fmaf(i1, __half2float(vj[NF]),   fmaf(i2, s_unit[t*3+1], aV1));
            aV2 = fmaf(i1, __half2float(vj[2*NF]), fmaf(i2, s_unit[t*3+2], aV2));
        }
    }
    const size_t o = (size_t)i*FDIM + f;
    s2[o]          = s1[o]          + accS;
    v2[o]          = v1[o]          + aV0;
    v2[o + NF]     = v1[o + NF]     + aV1;
    v2[o + 2*NF]   = v1[o + 2*NF]   + aV2;
}

// ---------------- combine (also refreshes fp16 v shadow) ---------------------
__global__ void k_combine(const float* __restrict__ s2, const float* __restrict__ v2,
                          const float* __restrict__ uvvv, const float* __restrict__ aw,
                          float* __restrict__ sOut, float* __restrict__ vOut,
                          __half* __restrict__ vOutH) {
    int idx = blockIdx.x*blockDim.x + threadIdx.x;
    if (idx >= NF) return;
    int n = idx >> 7, f = idx & 127;
    float a0 = aw[(size_t)n*PHI_D + f];
    float a1 = aw[(size_t)n*PHI_D + 128 + f];
    float a2 = aw[(size_t)n*PHI_D + 256 + f];
    float u0 = uvvv[((size_t)(0*NA+n))*256 + f];
    float u1 = uvvv[((size_t)(1*NA+n))*256 + f];
    float u2 = uvvv[((size_t)(2*NA+n))*256 + f];
    float w0 = uvvv[((size_t)(0*NA+n))*256 + 128 + f];
    float w1 = uvvv[((size_t)(1*NA+n))*256 + 128 + f];
    float w2 = uvvv[((size_t)(2*NA+n))*256 + 128 + f];
    float dot = u0*w0 + u1*w1 + u2*w2;
    sOut[idx] = s2[idx] + a1*dot + a2;
    float vo0 = v2[idx]        + u0*a0;
    float vo1 = v2[idx + NF]   + u1*a0;
    float vo2 = v2[idx + 2*NF] + u2*a0;
    vOut[idx]        = vo0;
    vOut[idx + NF]   = vo1;
    vOut[idx + 2*NF] = vo2;
    vOutH[idx]        = __float2half(vo0);
    vOutH[idx + NF]   = __float2half(vo1);
    vOutH[idx + 2*NF] = __float2half(vo2);
}

// ---------------- readout ----------------------------------------------------
__global__ void k_readout(const float* __restrict__ hid, const float* __restrict__ W2,
                          const float* __restrict__ b2, const int* __restrict__ mol,
                          float* __restrict__ out) {
    int n = blockIdx.x*blockDim.x + threadIdx.x;
    if (n >= NA) return;
    float acc = b2[0];
    const float* h = hid + (size_t)n*64;
    #pragma unroll
    for (int k = 0; k < 64; k++) acc = fmaf(h[k], W2[k], acc);
    atomicAdd(&out[mol[n]], acc);
}

// ---------------- host-side orchestration ------------------------------------
extern "C" void kernel_launch(void* const* d_in, const int* in_sizes, int n_in,
                              void* d_out, int out_size) {
    const float* xyz    = (const float*)d_in[0];
    const int*   z      = (const int*)  d_in[1];
    const int*   nbrs   = (const int*)  d_in[2];
    const int*   mol    = (const int*)  d_in[3];
    const float* emb    = (const float*)d_in[4];
    const float* msgW1  = (const float*)d_in[5];
    const float* msgb1  = (const float*)d_in[6];
    const float* msgW2  = (const float*)d_in[7];
    const float* msgb2  = (const float*)d_in[8];
    const float* distW  = (const float*)d_in[9];
    const float* distb  = (const float*)d_in[10];
    const float* updU   = (const float*)d_in[11];
    const float* updV   = (const float*)d_in[12];
    const float* updW1  = (const float*)d_in[13];
    const float* updb1  = (const float*)d_in[14];
    const float* updW2  = (const float*)d_in[15];
    const float* updb2  = (const float*)d_in[16];
    const float* readW1 = (const float*)d_in[17];
    const float* readb1 = (const float*)d_in[18];
    const float* readW2 = (const float*)d_in[19];
    const float* readb2 = (const float*)d_in[20];
    float* out = (float*)d_out;

    float *s1, *s2, *v1, *v2, *hid, *uvvv, *aw, *Bcat;
    __half *phih, *v1h;
    cudaGetSymbolAddress((void**)&s1,    g_s1);
    cudaGetSymbolAddress((void**)&s2,    g_s2);
    cudaGetSymbolAddress((void**)&v1,    g_v1);
    cudaGetSymbolAddress((void**)&v2,    g_v2);
    cudaGetSymbolAddress((void**)&phih,  g_phih);
    cudaGetSymbolAddress((void**)&v1h,   g_v1h);
    cudaGetSymbolAddress((void**)&hid,   g_hid);
    cudaGetSymbolAddress((void**)&uvvv,  g_uvvv);
    cudaGetSymbolAddress((void**)&aw,    g_aw);
    cudaGetSymbolAddress((void**)&Bcat,  g_Bcat);

    const int TPB = 256;
    const int GY1 = (NA + 127)/128;       // 79
    const int GY3 = (3*NA + 127)/128;     // 235

    // prep; launch #4 = gemm1 (clock probe)
    k_prep0<<<NF/TPB, TPB>>>(emb, z, updU, updV);                    // 1
    k_count<<<NE/TPB, TPB>>>(xyz, nbrs);                             // 2 (live edges only)
    k_scan <<<1, 1024>>>();                                          // 3
    k_tgemm<true, true, false><<<dim3(2, GY1), 256>>>(s1, msgW1, msgb1, hid, NA, 128, 128); // 4 (probe)
    k_fillgeom<<<NE/TPB, TPB>>>(xyz, nbrs);                          // 5 (live edges only)

    for (int l = 0; l < NLAYERS; l++) {
        const float* mW1 = msgW1 + (size_t)l*128*128;
        const float* mb1 = msgb1 + (size_t)l*128;
        const float* mW2 = msgW2 + (size_t)l*128*384;
        const float* mb2 = msgb2 + (size_t)l*384;
        const float* dW  = distW + (size_t)l*NRBF_K*384;
        const float* dbv = distb + (size_t)l*384;
        const float* uW1 = updW1 + (size_t)l*256*128;
        const float* ub1 = updb1 + (size_t)l*128;
        const float* uW2 = updW2 + (size_t)l*128*384;
        const float* ub2 = updb2 + (size_t)l*384;
        const float* Bc  = Bcat  + (size_t)l*128*256;

        if (l > 0)
            k_tgemm<true, true, false><<<dim3(2, GY1), 256>>>(s1, mW1, mb1, hid, NA, 128, 128);
        // phi GEMM writes fp16 directly
        k_tgemm<false, true, true><<<dim3(6, GY1), 256>>>(hid, mW2, mb2, phih, NA, 384, 128);
        // edge aggregation (CSR over LIVE edges only; fp16 gathers)
        k_edge<<<NA, 128>>>(dW, dbv, phih, s1, v1, v1h, s2, v2);
        // update phase: [uv | vv] in one GEMM (N=256)
        k_tgemm<false, false, false><<<dim3(4, GY3), 256>>>(v2, Bc, (const float*)nullptr, uvvv, 3*NA, 256, 128);
        // cat-GEMM with on-the-fly A = [s2 | vnorm(uvvv)]
        k_tgemm_cat<<<dim3(2, GY1), 256>>>(s2, uvvv, uW1, ub1, hid, NA, 128);
        k_tgemm<false, true, false><<<dim3(6, GY1), 256>>>(hid, uW2, ub2, aw,  NA, 384, 128);
        k_combine<<<NF/TPB, TPB>>>(s2, v2, uvvv, aw, s1, v1, v1h);
    }

    // readout
    k_tgemm<true, true, false><<<dim3(1, GY1), 256>>>(s1, readW1, readb1, hid, NA, 64, 128);
    cudaMemsetAsync(out, 0, NMOLS*sizeof(float));
    k_readout<<<(NA + TPB-1)/TPB, TPB>>>(hid, readW2, readb2, mol, out);
}